// round 7
// baseline (speedup 1.0000x reference)
#include <cuda_runtime.h>
#include <cuda_bf16.h>
#include <cstdint>

// ---------------------------------------------------------------------------
// APPNP (dense surrogate): N=8192, F=512, MLP=512, C=256, 2 MLP layers,
// 10 power iterations, alpha=0.1.
//   x = relu(A @ (x W0 + b0)); x = relu(A @ (x W1 + b1))
//   z0 = x Wout + bout;  repeat 10x: z = 0.9 A z + 0.1 z0;  out = softmax(z)
// Everything in bf16 with fp32 accumulation (see precision analysis: softmax
// logits have spread ~1e-5, so bf16 abs errors ~1e-6 are far below tolerance).
// ---------------------------------------------------------------------------

#define NN   8192
#define FD   512
#define CD   256
#define ALPHA 0.1f

// ---- scratch (static device globals; no allocations allowed) --------------
__device__ __nv_bfloat16 g_Abf[(size_t)NN * NN];     // 128 MB
__device__ __nv_bfloat16 g_Fbf[(size_t)NN * FD];     // 8 MB
__device__ __nv_bfloat16 g_W0bf[FD * FD];
__device__ __nv_bfloat16 g_W1bf[FD * FD];
__device__ __nv_bfloat16 g_Wobf[FD * CD];
__device__ __nv_bfloat16 g_Y[(size_t)NN * FD];       // xW+b intermediate
__device__ __nv_bfloat16 g_X[(size_t)NN * FD];       // relu(A(xW+b))
__device__ __nv_bfloat16 g_Z0[(size_t)NN * CD];
__device__ __nv_bfloat16 g_Za[(size_t)NN * CD];
__device__ __nv_bfloat16 g_Zb[(size_t)NN * CD];

// ---- fp32 -> bf16 conversion ----------------------------------------------
__global__ void f32_to_bf16_kernel(const float* __restrict__ src,
                                   __nv_bfloat16* __restrict__ dst, long n8) {
    long t = (long)blockIdx.x * blockDim.x + threadIdx.x;
    if (t >= n8) return;
    long i = t * 8;
    float4 a = *(const float4*)(src + i);
    float4 b = *(const float4*)(src + i + 4);
    union { int4 v; __nv_bfloat16 h[8]; } u;
    u.h[0] = __float2bfloat16(a.x); u.h[1] = __float2bfloat16(a.y);
    u.h[2] = __float2bfloat16(a.z); u.h[3] = __float2bfloat16(a.w);
    u.h[4] = __float2bfloat16(b.x); u.h[5] = __float2bfloat16(b.y);
    u.h[6] = __float2bfloat16(b.z); u.h[7] = __float2bfloat16(b.w);
    *(int4*)(dst + i) = u.v;
}

// ---- bf16 GEMM: C[M,N] = epilogue(A[M,K] @ B[K,N]) ------------------------
// A, B row-major bf16, fp32 accumulation via mma.sync.m16n8k16.
// MODE 0: C = acc + bias[col]           (store bf16)
// MODE 1: C = relu(acc)                 (store bf16)
// MODE 2: C = 0.9*acc + 0.1*Z0[row,col] (store bf16)
#define BM 128
#define BN 128
#define BK 32
#define ASTR 40   // smem row stride (elements): word-stride 20 -> conflict-free frag loads

template <int MODE>
__global__ void __launch_bounds__(256)
gemm_bf16_kernel(const __nv_bfloat16* __restrict__ A,
                 const __nv_bfloat16* __restrict__ B,
                 __nv_bfloat16* __restrict__ C,
                 int M, int N, int K,
                 const float* __restrict__ bias,
                 const __nv_bfloat16* __restrict__ Z0) {
    __shared__ __nv_bfloat16 As[BM * ASTR];   // [row][k]
    __shared__ __nv_bfloat16 Bs[BN * ASTR];   // [n][k] (transposed on store)

    const int tid  = threadIdx.x;
    const int lane = tid & 31;
    const int warp = tid >> 5;
    const int wm = (warp & 3) * 32;   // warp tile: 32 rows x 64 cols
    const int wn = (warp >> 2) * 64;

    const int bm0 = blockIdx.y * BM;
    const int bn0 = blockIdx.x * BN;

    float acc[2][8][4];
#pragma unroll
    for (int i = 0; i < 2; i++)
#pragma unroll
        for (int j = 0; j < 8; j++)
#pragma unroll
            for (int k = 0; k < 4; k++) acc[i][j][k] = 0.f;

    const int arow = lane >> 2;
    const int acol = (lane & 3) * 2;

    for (int k0 = 0; k0 < K; k0 += BK) {
        // --- A tile: 128x32, int4 (8 bf16) per load, 2 loads/thread ---
#pragma unroll
        for (int r = 0; r < 2; r++) {
            int idx = tid + r * 256;
            int row = idx >> 2;
            int c8  = (idx & 3) * 8;
            int4 v = *(const int4*)(A + (size_t)(bm0 + row) * K + k0 + c8);
            *(int4*)(&As[row * ASTR + c8]) = v;   // byte off = 80*row + 16*c -> 16B aligned
        }
        // --- B tile: 32x128, transpose into Bs[n][k] ---
#pragma unroll
        for (int r = 0; r < 2; r++) {
            int idx = tid + r * 256;
            int krow = idx >> 4;
            int n8   = (idx & 15) * 8;
            int4 v = *(const int4*)(B + (size_t)(k0 + krow) * N + bn0 + n8);
            union { int4 v; __nv_bfloat16 h[8]; } u; u.v = v;
#pragma unroll
            for (int i = 0; i < 8; i++)
                Bs[(n8 + i) * ASTR + krow] = u.h[i];
        }
        __syncthreads();

#pragma unroll
        for (int kk = 0; kk < BK; kk += 16) {
            uint32_t af[2][4], bf[8][2];
#pragma unroll
            for (int mi = 0; mi < 2; mi++) {
                const __nv_bfloat16* p = &As[(wm + mi * 16 + arow) * ASTR + kk + acol];
                af[mi][0] = *(const uint32_t*)(p);
                af[mi][1] = *(const uint32_t*)(p + 8 * ASTR);
                af[mi][2] = *(const uint32_t*)(p + 8);
                af[mi][3] = *(const uint32_t*)(p + 8 * ASTR + 8);
            }
#pragma unroll
            for (int nj = 0; nj < 8; nj++) {
                const __nv_bfloat16* p = &Bs[(wn + nj * 8 + arow) * ASTR + kk + acol];
                bf[nj][0] = *(const uint32_t*)(p);
                bf[nj][1] = *(const uint32_t*)(p + 8);
            }
#pragma unroll
            for (int mi = 0; mi < 2; mi++)
#pragma unroll
                for (int nj = 0; nj < 8; nj++) {
                    asm volatile(
                        "mma.sync.aligned.m16n8k16.row.col.f32.bf16.bf16.f32 "
                        "{%0,%1,%2,%3}, {%4,%5,%6,%7}, {%8,%9}, {%0,%1,%2,%3};\n"
                        : "+f"(acc[mi][nj][0]), "+f"(acc[mi][nj][1]),
                          "+f"(acc[mi][nj][2]), "+f"(acc[mi][nj][3])
                        : "r"(af[mi][0]), "r"(af[mi][1]), "r"(af[mi][2]), "r"(af[mi][3]),
                          "r"(bf[nj][0]), "r"(bf[nj][1]));
                }
        }
        __syncthreads();
    }

    // --- epilogue ---
#pragma unroll
    for (int mi = 0; mi < 2; mi++) {
#pragma unroll
        for (int nj = 0; nj < 8; nj++) {
            int row0 = bm0 + wm + mi * 16 + arow;
            int col0 = bn0 + wn + nj * 8 + acol;
#pragma unroll
            for (int h = 0; h < 2; h++) {
                int row = row0 + h * 8;
                float v0 = acc[mi][nj][2 * h + 0];
                float v1 = acc[mi][nj][2 * h + 1];
                if (MODE == 0) { v0 += bias[col0]; v1 += bias[col0 + 1]; }
                if (MODE == 1) { v0 = fmaxf(v0, 0.f); v1 = fmaxf(v1, 0.f); }
                if (MODE == 2) {
                    v0 = (1.f - ALPHA) * v0 + ALPHA * __bfloat162float(Z0[(size_t)row * N + col0]);
                    v1 = (1.f - ALPHA) * v1 + ALPHA * __bfloat162float(Z0[(size_t)row * N + col0 + 1]);
                }
                __nv_bfloat162 o = __floats2bfloat162_rn(v0, v1);
                *(__nv_bfloat162*)(C + (size_t)row * N + col0) = o;
            }
        }
    }
}

// ---- row softmax over C=256, one block (256 threads) per row --------------
__global__ void softmax_kernel(const __nv_bfloat16* __restrict__ Z,
                               float* __restrict__ out) {
    int row = blockIdx.x;
    int tid = threadIdx.x;
    float v = __bfloat162float(Z[(size_t)row * CD + tid]);

    __shared__ float red[8], red2[8];
    float m = v;
#pragma unroll
    for (int o = 16; o > 0; o >>= 1) m = fmaxf(m, __shfl_xor_sync(0xffffffffu, m, o));
    if ((tid & 31) == 0) red[tid >> 5] = m;
    __syncthreads();
    float bm = red[0];
#pragma unroll
    for (int i = 1; i < 8; i++) bm = fmaxf(bm, red[i]);

    float e = __expf(v - bm);
    float s = e;
#pragma unroll
    for (int o = 16; o > 0; o >>= 1) s += __shfl_xor_sync(0xffffffffu, s, o);
    if ((tid & 31) == 0) red2[tid >> 5] = s;
    __syncthreads();
    float bs = 0.f;
#pragma unroll
    for (int i = 0; i < 8; i++) bs += red2[i];

    out[(size_t)row * CD + tid] = e / bs;
}

// ---------------------------------------------------------------------------
extern "C" void kernel_launch(void* const* d_in, const int* in_sizes, int n_in,
                              void* d_out, int out_size) {
    const float* features = (const float*)d_in[0];   // [8192, 512]
    const float* fltr     = (const float*)d_in[1];   // [8192, 8192]
    const float* W0       = (const float*)d_in[2];   // [512, 512]
    const float* b0       = (const float*)d_in[3];   // [512]
    const float* W1       = (const float*)d_in[4];   // [512, 512]
    const float* b1       = (const float*)d_in[5];   // [512]
    const float* Wo       = (const float*)d_in[6];   // [512, 256]
    const float* bo       = (const float*)d_in[7];   // [256]

    void *pA, *pF, *pW0, *pW1, *pWo, *pY, *pX, *pZ0, *pZa, *pZb;
    cudaGetSymbolAddress(&pA,  g_Abf);
    cudaGetSymbolAddress(&pF,  g_Fbf);
    cudaGetSymbolAddress(&pW0, g_W0bf);
    cudaGetSymbolAddress(&pW1, g_W1bf);
    cudaGetSymbolAddress(&pWo, g_Wobf);
    cudaGetSymbolAddress(&pY,  g_Y);
    cudaGetSymbolAddress(&pX,  g_X);
    cudaGetSymbolAddress(&pZ0, g_Z0);
    cudaGetSymbolAddress(&pZa, g_Za);
    cudaGetSymbolAddress(&pZb, g_Zb);

    __nv_bfloat16* Abf = (__nv_bfloat16*)pA;
    __nv_bfloat16* Fbf = (__nv_bfloat16*)pF;
    __nv_bfloat16* W0b = (__nv_bfloat16*)pW0;
    __nv_bfloat16* W1b = (__nv_bfloat16*)pW1;
    __nv_bfloat16* Wob = (__nv_bfloat16*)pWo;
    __nv_bfloat16* Yb  = (__nv_bfloat16*)pY;
    __nv_bfloat16* Xb  = (__nv_bfloat16*)pX;
    __nv_bfloat16* Z0b = (__nv_bfloat16*)pZ0;
    __nv_bfloat16* Zab = (__nv_bfloat16*)pZa;
    __nv_bfloat16* Zbb = (__nv_bfloat16*)pZb;

    auto cvt = [](const float* s, __nv_bfloat16* d, long n) {
        long n8 = n / 8;
        int blocks = (int)((n8 + 255) / 256);
        f32_to_bf16_kernel<<<blocks, 256>>>(s, d, n8);
    };

    // 0) convert inputs to bf16
    cvt(fltr,     Abf, (long)NN * NN);
    cvt(features, Fbf, (long)NN * FD);
    cvt(W0,       W0b, FD * FD);
    cvt(W1,       W1b, FD * FD);
    cvt(Wo,       Wob, FD * CD);

    dim3 gridS(FD / BN, NN / BM);   // N=512 GEMMs
    dim3 gridC(CD / BN, NN / BM);   // N=256 GEMMs

    // 1) Y = features @ W0 + b0
    gemm_bf16_kernel<0><<<gridS, 256>>>(Fbf, W0b, Yb, NN, FD, FD, b0, nullptr);
    // 2) X = relu(A @ Y)
    gemm_bf16_kernel<1><<<gridS, 256>>>(Abf, Yb, Xb, NN, FD, NN, nullptr, nullptr);
    // 3) Y = X @ W1 + b1
    gemm_bf16_kernel<0><<<gridS, 256>>>(Xb, W1b, Yb, NN, FD, FD, b1, nullptr);
    // 4) X = relu(A @ Y)
    gemm_bf16_kernel<1><<<gridS, 256>>>(Abf, Yb, Xb, NN, FD, NN, nullptr, nullptr);
    // 5) Z0 = X @ Wo + bo
    gemm_bf16_kernel<0><<<gridC, 256>>>(Xb, Wob, Z0b, NN, CD, FD, bo, nullptr);

    // 6) 10x: Z = 0.9 * A @ Z + 0.1 * Z0
    __nv_bfloat16* zin = Z0b;
    __nv_bfloat16* zout = Zab;
    for (int it = 0; it < 10; it++) {
        gemm_bf16_kernel<2><<<gridC, 256>>>(Abf, zin, zout, NN, CD, NN, nullptr, Z0b);
        zin = zout;
        zout = (zin == Zab) ? Zbb : Zab;
    }

    // 7) softmax rows -> fp32 output
    softmax_kernel<<<NN, 256>>>(zin, (float*)d_out);
}

// round 8
// speedup vs baseline: 2.9413x; 2.9413x over previous
#include <cuda_runtime.h>
#include <cuda_bf16.h>
#include <cstdint>

// ---------------------------------------------------------------------------
// APPNP dense surrogate, N=8192, F=MLP=512, C=256, 10 power iters, alpha=0.1.
// All heavy math in bf16 + fp32 accumulation (logit budget analysis: bf16
// injects ~1e-6 abs logit error vs ~1e-3 tolerance).
//
// Transposed-activation trick: alternate natural / transposed storage so that
// EVERY GEMM's B operand is already K-major [N,K] in memory:
//   Yt  = W0t @ (B=Ft,  Bt stored = F natural)        [512 ,8192]  +b0(row)
//   X   = A   @ (B=Y,   Bt stored = Yt)               [8192, 512]  relu
//   Yt  = W1t @ (B=Xt,  Bt stored = X natural)        [512 ,8192]  +b1(row)
//   X   = A   @ (B=Y2,  Bt stored = Yt)               [8192, 512]  relu
//   Z0t = Wot @ (B=X2t, Bt stored = X natural)        [256 ,8192]  +bo(row)
//   Zt  = Zt  @ (B=At,  Bt stored = A natural!) *0.9 + 0.1*Z0t  (x10)
//   out = column-softmax of Zt, written transposed    [8192, 256] fp32
// => zero transpose kernels; only tiny W matrices get transposing converts.
// ---------------------------------------------------------------------------

#define NN   8192
#define FD   512
#define CD   256
#define ALPHA 0.1f

#define BM 128
#define BN 128
#define BK 32
#define ASTR 40                                  // padded smem stride (elems)
#define STAGES 4
#define STAGE_ELS (BM * ASTR)                    // 5120 elems / tile / stage
#define SMEM_BYTES (STAGES * 2 * STAGE_ELS * 2)  // 81920 B

// ---- scratch (static device globals; allocations are forbidden) -----------
__device__ __nv_bfloat16 g_Abf[(size_t)NN * NN];     // 128 MB
__device__ __nv_bfloat16 g_Fbf[(size_t)NN * FD];
__device__ __nv_bfloat16 g_W0t[FD * FD];
__device__ __nv_bfloat16 g_W1t[FD * FD];
__device__ __nv_bfloat16 g_Wot[FD * CD];
__device__ __nv_bfloat16 g_Yt[(size_t)FD * NN];      // transposed xW+b
__device__ __nv_bfloat16 g_X[(size_t)NN * FD];       // relu(A Y), natural
__device__ __nv_bfloat16 g_Z0t[(size_t)CD * NN];
__device__ __nv_bfloat16 g_Za[(size_t)CD * NN];
__device__ __nv_bfloat16 g_Zb[(size_t)CD * NN];

__device__ __forceinline__ uint32_t sptr(const void* p) {
    return (uint32_t)__cvta_generic_to_shared(p);
}

// ---- fp32 -> bf16 (vectorized) --------------------------------------------
__global__ void f32_to_bf16_kernel(const float* __restrict__ src,
                                   __nv_bfloat16* __restrict__ dst, long n8) {
    long t = (long)blockIdx.x * blockDim.x + threadIdx.x;
    if (t >= n8) return;
    long i = t * 8;
    float4 a = *(const float4*)(src + i);
    float4 b = *(const float4*)(src + i + 4);
    union { int4 v; __nv_bfloat16 h[8]; } u;
    u.h[0] = __float2bfloat16(a.x); u.h[1] = __float2bfloat16(a.y);
    u.h[2] = __float2bfloat16(a.z); u.h[3] = __float2bfloat16(a.w);
    u.h[4] = __float2bfloat16(b.x); u.h[5] = __float2bfloat16(b.y);
    u.h[6] = __float2bfloat16(b.z); u.h[7] = __float2bfloat16(b.w);
    *(int4*)(dst + i) = u.v;
}

// ---- fp32 [R,C] -> bf16 transposed [C,R] ----------------------------------
__global__ void f32_to_bf16_T_kernel(const float* __restrict__ src,
                                     __nv_bfloat16* __restrict__ dst,
                                     int R, int C) {
    __shared__ float t[32][33];
    int c0 = blockIdx.x * 32, r0 = blockIdx.y * 32;
    int tx = threadIdx.x, ty = threadIdx.y;   // block (32, 8)
#pragma unroll
    for (int j = 0; j < 32; j += 8)
        t[ty + j][tx] = src[(size_t)(r0 + ty + j) * C + c0 + tx];
    __syncthreads();
#pragma unroll
    for (int j = 0; j < 32; j += 8)
        dst[(size_t)(c0 + ty + j) * R + r0 + tx] = __float2bfloat16(t[tx][ty + j]);
}

// ---- pipelined bf16 GEMM: C[M,N] = epi(Aop[M,K] @ B), B given as Bt[N,K] --
// MODE 0: acc + bias[row]   MODE 1: relu(acc)   MODE 2: 0.9*acc + 0.1*Z0[r,c]
template <int MODE>
__global__ void __launch_bounds__(256)
gemm_bf16_kernel(const __nv_bfloat16* __restrict__ Aop,
                 const __nv_bfloat16* __restrict__ Btp,
                 __nv_bfloat16* __restrict__ C,
                 int M, int N, int K,
                 const float* __restrict__ bias,
                 const __nv_bfloat16* __restrict__ Z0) {
    extern __shared__ __nv_bfloat16 dsm[];
    __nv_bfloat16* As = dsm;                       // STAGES x [128][ASTR]
    __nv_bfloat16* Bs = dsm + STAGES * STAGE_ELS;  // STAGES x [128][ASTR]

    const int tid  = threadIdx.x;
    const int lane = tid & 31;
    const int warp = tid >> 5;
    const int wm = (warp & 3) * 32;    // warp tile 32 x 64
    const int wn = (warp >> 2) * 64;
    const int bm0 = blockIdx.y * BM;
    const int bn0 = blockIdx.x * BN;

    const int nIter = K / BK;

    auto load_stage = [&](int st, int kiter) {
        const int k0 = kiter * BK;
        __nv_bfloat16* Asb = As + st * STAGE_ELS;
        __nv_bfloat16* Bsb = Bs + st * STAGE_ELS;
#pragma unroll
        for (int r = 0; r < 2; r++) {
            int idx = tid + r * 256;
            int row = idx >> 2;
            int c8  = (idx & 3) * 8;
            uint32_t da = sptr(Asb + row * ASTR + c8);
            const void* ga = Aop + (size_t)(bm0 + row) * K + k0 + c8;
            asm volatile("cp.async.cg.shared.global [%0], [%1], 16;\n"
                         :: "r"(da), "l"(ga));
            uint32_t db = sptr(Bsb + row * ASTR + c8);
            const void* gb = Btp + (size_t)(bn0 + row) * K + k0 + c8;
            asm volatile("cp.async.cg.shared.global [%0], [%1], 16;\n"
                         :: "r"(db), "l"(gb));
        }
        asm volatile("cp.async.commit_group;\n");
    };

    float acc[2][8][4];
#pragma unroll
    for (int i = 0; i < 2; i++)
#pragma unroll
        for (int j = 0; j < 8; j++)
#pragma unroll
            for (int k = 0; k < 4; k++) acc[i][j][k] = 0.f;

    const int arow = lane >> 2;
    const int acol = (lane & 3) * 2;

#pragma unroll
    for (int s = 0; s < STAGES - 1; s++) load_stage(s, s);

    for (int it = 0; it < nIter; it++) {
        asm volatile("cp.async.wait_group %0;\n" :: "n"(STAGES - 2));
        __syncthreads();

        int nxt = it + STAGES - 1;
        if (nxt < nIter) load_stage(nxt % STAGES, nxt);
        else asm volatile("cp.async.commit_group;\n");   // keep group count

        const __nv_bfloat16* Asb = As + (it % STAGES) * STAGE_ELS;
        const __nv_bfloat16* Bsb = Bs + (it % STAGES) * STAGE_ELS;

#pragma unroll
        for (int kk = 0; kk < BK; kk += 16) {
            uint32_t af[2][4], bf[8][2];
#pragma unroll
            for (int mi = 0; mi < 2; mi++) {
                const __nv_bfloat16* p = &Asb[(wm + mi * 16 + arow) * ASTR + kk + acol];
                af[mi][0] = *(const uint32_t*)(p);
                af[mi][1] = *(const uint32_t*)(p + 8 * ASTR);
                af[mi][2] = *(const uint32_t*)(p + 8);
                af[mi][3] = *(const uint32_t*)(p + 8 * ASTR + 8);
            }
#pragma unroll
            for (int nj = 0; nj < 8; nj++) {
                const __nv_bfloat16* p = &Bsb[(wn + nj * 8 + arow) * ASTR + kk + acol];
                bf[nj][0] = *(const uint32_t*)(p);
                bf[nj][1] = *(const uint32_t*)(p + 8);
            }
#pragma unroll
            for (int mi = 0; mi < 2; mi++)
#pragma unroll
                for (int nj = 0; nj < 8; nj++) {
                    asm volatile(
                        "mma.sync.aligned.m16n8k16.row.col.f32.bf16.bf16.f32 "
                        "{%0,%1,%2,%3}, {%4,%5,%6,%7}, {%8,%9}, {%0,%1,%2,%3};\n"
                        : "+f"(acc[mi][nj][0]), "+f"(acc[mi][nj][1]),
                          "+f"(acc[mi][nj][2]), "+f"(acc[mi][nj][3])
                        : "r"(af[mi][0]), "r"(af[mi][1]), "r"(af[mi][2]), "r"(af[mi][3]),
                          "r"(bf[nj][0]), "r"(bf[nj][1]));
                }
        }
    }

    // --- epilogue ---
#pragma unroll
    for (int mi = 0; mi < 2; mi++) {
#pragma unroll
        for (int nj = 0; nj < 8; nj++) {
            int row0 = bm0 + wm + mi * 16 + arow;
            int col0 = bn0 + wn + nj * 8 + acol;
#pragma unroll
            for (int h = 0; h < 2; h++) {
                int row = row0 + h * 8;
                float v0 = acc[mi][nj][2 * h + 0];
                float v1 = acc[mi][nj][2 * h + 1];
                if (MODE == 0) { float b = bias[row]; v0 += b; v1 += b; }
                if (MODE == 1) { v0 = fmaxf(v0, 0.f); v1 = fmaxf(v1, 0.f); }
                if (MODE == 2) {
                    v0 = (1.f - ALPHA) * v0 + ALPHA * __bfloat162float(Z0[(size_t)row * N + col0]);
                    v1 = (1.f - ALPHA) * v1 + ALPHA * __bfloat162float(Z0[(size_t)row * N + col0 + 1]);
                }
                *(__nv_bfloat162*)(C + (size_t)row * N + col0) = __floats2bfloat162_rn(v0, v1);
            }
        }
    }
}

// ---- column softmax of Zt[256, 8192] -> out[8192, 256] fp32 ---------------
// block = 64 threads (2 warps), each warp owns 32 columns; smem-tiled
// transposed writeback so output stores are coalesced.
__global__ void softmax_T_kernel(const __nv_bfloat16* __restrict__ Zt,
                                 float* __restrict__ out) {
    __shared__ float tile[2][32][33];
    int warp = threadIdx.x >> 5, lane = threadIdx.x & 31;
    int n0 = blockIdx.x * 64 + warp * 32;
    int n = n0 + lane;

    float mx = -1e30f;
#pragma unroll 8
    for (int c = 0; c < CD; c++)
        mx = fmaxf(mx, __bfloat162float(Zt[(size_t)c * NN + n]));
    float s = 0.f;
#pragma unroll 8
    for (int c = 0; c < CD; c++)
        s += __expf(__bfloat162float(Zt[(size_t)c * NN + n]) - mx);
    float inv = 1.f / s;

    for (int c0 = 0; c0 < CD; c0 += 32) {
#pragma unroll
        for (int cc = 0; cc < 32; cc++)
            tile[warp][cc][lane] =
                __expf(__bfloat162float(Zt[(size_t)(c0 + cc) * NN + n]) - mx) * inv;
        __syncwarp();
#pragma unroll
        for (int i = 0; i < 32; i++)
            out[(size_t)(n0 + i) * CD + c0 + lane] = tile[warp][lane][i];
        __syncwarp();
    }
}

// ---------------------------------------------------------------------------
extern "C" void kernel_launch(void* const* d_in, const int* in_sizes, int n_in,
                              void* d_out, int out_size) {
    const float* features = (const float*)d_in[0];   // [8192, 512]
    const float* fltr     = (const float*)d_in[1];   // [8192, 8192]
    const float* W0       = (const float*)d_in[2];   // [512, 512]
    const float* b0       = (const float*)d_in[3];
    const float* W1       = (const float*)d_in[4];   // [512, 512]
    const float* b1       = (const float*)d_in[5];
    const float* Wo       = (const float*)d_in[6];   // [512, 256]
    const float* bo       = (const float*)d_in[7];

    void *pA, *pF, *pW0, *pW1, *pWo, *pYt, *pX, *pZ0, *pZa, *pZb;
    cudaGetSymbolAddress(&pA,  g_Abf);
    cudaGetSymbolAddress(&pF,  g_Fbf);
    cudaGetSymbolAddress(&pW0, g_W0t);
    cudaGetSymbolAddress(&pW1, g_W1t);
    cudaGetSymbolAddress(&pWo, g_Wot);
    cudaGetSymbolAddress(&pYt, g_Yt);
    cudaGetSymbolAddress(&pX,  g_X);
    cudaGetSymbolAddress(&pZ0, g_Z0t);
    cudaGetSymbolAddress(&pZa, g_Za);
    cudaGetSymbolAddress(&pZb, g_Zb);

    __nv_bfloat16* Abf = (__nv_bfloat16*)pA;
    __nv_bfloat16* Fbf = (__nv_bfloat16*)pF;
    __nv_bfloat16* W0t = (__nv_bfloat16*)pW0;
    __nv_bfloat16* W1t = (__nv_bfloat16*)pW1;
    __nv_bfloat16* Wot = (__nv_bfloat16*)pWo;
    __nv_bfloat16* Yt  = (__nv_bfloat16*)pYt;
    __nv_bfloat16* Xb  = (__nv_bfloat16*)pX;
    __nv_bfloat16* Z0t = (__nv_bfloat16*)pZ0;
    __nv_bfloat16* Za  = (__nv_bfloat16*)pZa;
    __nv_bfloat16* Zb  = (__nv_bfloat16*)pZb;

    // opt-in to 80KB dynamic smem (idempotent; not a stream op -> capture-safe)
    cudaFuncSetAttribute(gemm_bf16_kernel<0>,
                         cudaFuncAttributeMaxDynamicSharedMemorySize, SMEM_BYTES);
    cudaFuncSetAttribute(gemm_bf16_kernel<1>,
                         cudaFuncAttributeMaxDynamicSharedMemorySize, SMEM_BYTES);
    cudaFuncSetAttribute(gemm_bf16_kernel<2>,
                         cudaFuncAttributeMaxDynamicSharedMemorySize, SMEM_BYTES);

    auto cvt = [](const float* s, __nv_bfloat16* d, long n) {
        long n8 = n / 8;
        f32_to_bf16_kernel<<<(int)((n8 + 255) / 256), 256>>>(s, d, n8);
    };

    // 0) converts
    cvt(fltr,     Abf, (long)NN * NN);
    cvt(features, Fbf, (long)NN * FD);
    f32_to_bf16_T_kernel<<<dim3(FD / 32, FD / 32), dim3(32, 8)>>>(W0, W0t, FD, FD);
    f32_to_bf16_T_kernel<<<dim3(FD / 32, FD / 32), dim3(32, 8)>>>(W1, W1t, FD, FD);
    f32_to_bf16_T_kernel<<<dim3(CD / 32, FD / 32), dim3(32, 8)>>>(Wo, Wot, FD, CD);

    dim3 gridYt(NN / BN, FD / BM);   // [512, 8192] outputs
    dim3 gridX (FD / BN, NN / BM);   // [8192, 512] outputs
    dim3 gridZ (NN / BN, CD / BM);   // [256, 8192] outputs

    // 1) Yt = W0t @ Ft   (+b0 per row)
    gemm_bf16_kernel<0><<<gridYt, 256, SMEM_BYTES>>>(W0t, Fbf, Yt, FD, NN, FD, b0, nullptr);
    // 2) X = relu(A @ Y)   (Bt = Yt)
    gemm_bf16_kernel<1><<<gridX, 256, SMEM_BYTES>>>(Abf, Yt, Xb, NN, FD, NN, nullptr, nullptr);
    // 3) Yt = W1t @ Xt   (+b1 per row; Bt = X)
    gemm_bf16_kernel<0><<<gridYt, 256, SMEM_BYTES>>>(W1t, Xb, Yt, FD, NN, FD, b1, nullptr);
    // 4) X = relu(A @ Y2)
    gemm_bf16_kernel<1><<<gridX, 256, SMEM_BYTES>>>(Abf, Yt, Xb, NN, FD, NN, nullptr, nullptr);
    // 5) Z0t = Wot @ X2t   (+bo per row; Bt = X)
    gemm_bf16_kernel<0><<<gridZ, 256, SMEM_BYTES>>>(Wot, Xb, Z0t, CD, NN, FD, bo, nullptr);

    // 6) 10x: Zt = 0.9 * Zt @ At + 0.1 * Z0t   (Bt = A natural!)
    __nv_bfloat16* zin = Z0t;
    __nv_bfloat16* zout = Za;
    for (int it = 0; it < 10; it++) {
        gemm_bf16_kernel<2><<<gridZ, 256, SMEM_BYTES>>>(zin, Abf, zout, CD, NN, NN, nullptr, Z0t);
        zin = zout;
        zout = (zin == Za) ? Zb : Za;
    }

    // 7) column softmax -> natural [8192, 256] fp32
    softmax_T_kernel<<<NN / 64, 64>>>(zin, (float*)d_out);
}